// round 8
// baseline (speedup 1.0000x reference)
#include <cuda_runtime.h>

#define HID   50
#define SEQT  512
#define NG    5            // unit-groups per block (100 threads each)
#define NB    10           // batch elements per block (2 per group)
#define BLOCK 512
#define ROWP  52           // padded h row (floats)

// packed 2xfp32 FMA: d = a*b + c
__device__ __forceinline__ unsigned long long fma2(unsigned long long a,
                                                   unsigned long long b,
                                                   unsigned long long c) {
    unsigned long long d;
    asm("fma.rn.f32x2 %0, %1, %2, %3;" : "=l"(d) : "l"(a), "l"(b), "l"(c));
    return d;
}
__device__ __forceinline__ float hsum2(unsigned long long v) {
    float lo, hi;
    asm("mov.b64 {%0, %1}, %2;" : "=f"(lo), "=f"(hi) : "l"(v));
    return lo + hi;
}
__device__ __forceinline__ float tanhapx(float x) {
    float y;
    asm("tanh.approx.f32 %0, %1;" : "=f"(y) : "f"(x));
    return y;
}
__device__ __forceinline__ float sigapx(float x) {
    return __fmaf_rn(0.5f, tanhapx(0.5f * x), 0.5f);
}

__global__ void __launch_bounds__(BLOCK, 1)
lstm_fused_kernel(const float* __restrict__ x,
                  const float* __restrict__ W_ih,
                  const float* __restrict__ W_hh,
                  const float* __restrict__ b_ih,
                  const float* __restrict__ b_hh,
                  const float* __restrict__ W_out,
                  const float* __restrict__ b_out,
                  float* __restrict__ out,
                  int B)
{
    // h rows 0..4 = stream A of groups 0..4; rows 5..9 = stream B
    __shared__ __align__(16) float sh_h[2][NB][ROWP];
    __shared__ __align__(16) float sh_wout[ROWP];

    const int tid = threadIdx.x;
    int grp = tid / 100;             // 0..4 gate groups; 5 = tail lanes
    int r   = tid - grp * 100;       // 0..99
    const bool gate_lane = (grp < NG);
    if (!gate_lane) { grp = 0; r = 0; }
    const int j  = r >> 1;           // hidden unit 0..49
    const int gp = r & 1;            // 0 -> gates {i,f}; 1 -> gates {g,o}

    const int base = blockIdx.x * NB;
    const int bA = base + grp;
    const int bB = bA + NG;
    const bool actA = gate_lane && (bA < B);
    const bool actB = gate_lane && (bB < B);

    // output-projection lanes: tids 500..509 handle h rows 0..9
    const int olane = tid - NG * 100;
    const bool out_lane = (tid >= NG * 100) && (olane < NB) && (base + olane < B);

    // ---- one-time init ----
    for (int i = tid; i < 2 * NB * ROWP; i += BLOCK)
        (&sh_h[0][0][0])[i] = 0.0f;
    if (tid < ROWP)
        sh_wout[tid] = (tid < HID) ? W_out[tid] : 0.0f;

    // 2 W_hh gate rows for this thread, as f32 pairs (shared by both streams)
    unsigned long long w2[2][25];
    float wih[2], bs[2];
    if (gate_lane) {
        #pragma unroll
        for (int gg = 0; gg < 2; gg++) {
            const int row = (gp * 2 + gg) * HID + j;  // gate order: i, f, g, o
            wih[gg] = W_ih[row];
            bs[gg]  = b_ih[row] + b_hh[row];
            const unsigned long long* wrow =
                reinterpret_cast<const unsigned long long*>(W_hh + row * HID);
            #pragma unroll
            for (int p = 0; p < 25; p++)
                w2[gg][p] = wrow[p];
        }
    }
    const float bout = b_out[0];

    const float* __restrict__ xrowA = x + (size_t)(actA ? bA : 0) * SEQT;
    const float* __restrict__ xrowB = x + (size_t)(actB ? bB : 0) * SEQT;
    float* __restrict__ orow = out + (size_t)(out_lane ? (base + olane) : 0) * SEQT;

    float c = 0.0f;      // even lane: c of stream A; odd lane: c of stream B
    int cur = 0;

    __syncthreads();

    for (int t = 0; t < SEQT; t++) {
        const int nxt = cur ^ 1;

        if (gate_lane) {
            const float xA = xrowA[t];
            const float xB = xrowB[t];

            const float* hA = &sh_h[cur][grp][0];          // B row at +NG*ROWP
            unsigned long long aA0 = 0ull, aA1 = 0ull, aB0 = 0ull, aB1 = 0ull;

            #pragma unroll
            for (int q = 0; q < 12; q++) {
                const ulonglong2 hvA =
                    *reinterpret_cast<const ulonglong2*>(hA + q * 4);
                const ulonglong2 hvB =
                    *reinterpret_cast<const ulonglong2*>(hA + NG * ROWP + q * 4);
                aA0 = fma2(hvA.x, w2[0][2*q],   aA0);
                aB0 = fma2(hvB.x, w2[0][2*q],   aB0);
                aA1 = fma2(hvA.x, w2[1][2*q],   aA1);
                aB1 = fma2(hvB.x, w2[1][2*q],   aB1);
                aA0 = fma2(hvA.y, w2[0][2*q+1], aA0);
                aB0 = fma2(hvB.y, w2[0][2*q+1], aB0);
                aA1 = fma2(hvA.y, w2[1][2*q+1], aA1);
                aB1 = fma2(hvB.y, w2[1][2*q+1], aB1);
            }
            {
                const unsigned long long hvA =
                    *reinterpret_cast<const unsigned long long*>(hA + 48);
                const unsigned long long hvB =
                    *reinterpret_cast<const unsigned long long*>(hA + NG * ROWP + 48);
                aA0 = fma2(hvA, w2[0][24], aA0);
                aB0 = fma2(hvB, w2[0][24], aB0);
                aA1 = fma2(hvA, w2[1][24], aA1);
                aB1 = fma2(hvB, w2[1][24], aB1);
            }

            // pre-activations for this thread's 2 gates, both streams
            const float pA0 = hsum2(aA0) + __fmaf_rn(xA, wih[0], bs[0]);
            const float pA1 = hsum2(aA1) + __fmaf_rn(xA, wih[1], bs[1]);
            const float pB0 = hsum2(aB0) + __fmaf_rn(xB, wih[0], bs[0]);
            const float pB1 = hsum2(aB1) + __fmaf_rn(xB, wih[1], bs[1]);

            // even (gp0): u = sig(iA), sig(fA), sig(iB), sig(fB)
            // odd  (gp1): u = tanh(gA), sig(oA), tanh(gB), sig(oB)
            float u0, u1, u2, u3;
            if (gp == 0) {
                u0 = sigapx(pA0); u1 = sigapx(pA1);
                u2 = sigapx(pB0); u3 = sigapx(pB1);
            } else {
                u0 = tanhapx(pA0); u1 = sigapx(pA1);
                u2 = tanhapx(pB0); u3 = sigapx(pB1);
            }

            // exchange: even sends B-gates (u2,u3), receives (tanh gA, sig oA);
            //           odd sends A-gates (u0,u1), receives (sig iB, sig fB)
            const float s0 = gp ? u0 : u2;
            const float s1 = gp ? u1 : u3;
            const unsigned m = __activemask();
            const float r0 = __shfl_xor_sync(m, s0, 1);
            const float r1 = __shfl_xor_sync(m, s1, 1);

            if (gp == 0) {
                // stream A: i=u0, f=u1, tanh(g)=r0, sig(o)=r1
                c = __fmaf_rn(u1, c, u0 * r0);
                const float hn = r1 * tanhapx(c);
                if (actA) sh_h[nxt][grp][j] = hn;
            } else {
                // stream B: tanh(g)=u2, sig(o)=u3, i=r0, f=r1
                c = __fmaf_rn(r1, c, r0 * u2);
                const float hn = u3 * tanhapx(c);
                if (actB) sh_h[nxt][grp + NG][j] = hn;
            }
        } else if (out_lane && t > 0) {
            // out[t-1] = h_{t-1} . wout + bout, concurrent with gate compute
            const float* hp = &sh_h[cur][olane][0];
            float y0 = bout, y1 = 0.0f, y2 = 0.0f, y3 = 0.0f;
            #pragma unroll
            for (int kq = 0; kq < 13; kq++) {       // pads are zero in both
                const float4 hv = *reinterpret_cast<const float4*>(hp + kq * 4);
                const float4 wv = *reinterpret_cast<const float4*>(sh_wout + kq * 4);
                y0 = __fmaf_rn(hv.x, wv.x, y0);
                y1 = __fmaf_rn(hv.y, wv.y, y1);
                y2 = __fmaf_rn(hv.z, wv.z, y2);
                y3 = __fmaf_rn(hv.w, wv.w, y3);
            }
            orow[t - 1] = (y0 + y1) + (y2 + y3);
        }

        __syncthreads();
        cur = nxt;
    }

    // final output element from the last h buffer
    if (out_lane) {
        const float* hp = &sh_h[cur][olane][0];
        float y0 = bout, y1 = 0.0f, y2 = 0.0f, y3 = 0.0f;
        #pragma unroll
        for (int kq = 0; kq < 13; kq++) {
            const float4 hv = *reinterpret_cast<const float4*>(hp + kq * 4);
            const float4 wv = *reinterpret_cast<const float4*>(sh_wout + kq * 4);
            y0 = __fmaf_rn(hv.x, wv.x, y0);
            y1 = __fmaf_rn(hv.y, wv.y, y1);
            y2 = __fmaf_rn(hv.z, wv.z, y2);
            y3 = __fmaf_rn(hv.w, wv.w, y3);
        }
        orow[SEQT - 1] = (y0 + y1) + (y2 + y3);
    }
}

extern "C" void kernel_launch(void* const* d_in, const int* in_sizes, int n_in,
                              void* d_out, int out_size)
{
    const float* x     = (const float*)d_in[0];
    const float* W_ih  = (const float*)d_in[1];
    const float* W_hh  = (const float*)d_in[2];
    const float* b_ih  = (const float*)d_in[3];
    const float* b_hh  = (const float*)d_in[4];
    const float* W_out = (const float*)d_in[5];
    const float* b_out = (const float*)d_in[6];
    float* out = (float*)d_out;

    const int B = in_sizes[0] / SEQT;          // I == 1, x is [B, T, 1]
    const int grid = (B + NB - 1) / NB;
    lstm_fused_kernel<<<grid, BLOCK>>>(x, W_ih, W_hh, b_ih, b_hh, W_out, b_out, out, B);
}